// round 2
// baseline (speedup 1.0000x reference)
#include <cuda_runtime.h>
#include <math.h>

#define IMGS   457
#define HPAD   464
#define HP     29          // patches per side
#define NTOK   841         // 29*29
#define BATCH  8
#define DIM    256
#define MTOK   (BATCH*NTOK)   // 6728
#define NHEADS 8
#define DH     32

// ---------------- scratch (device globals; no allocations) ----------------
__device__ float g_tok [MTOK*1280]; // patch token vectors
__device__ float g_t   [MTOK*DIM];  // residual stream
__device__ float g_ln  [MTOK*DIM];  // layernorm output
__device__ float g_qkv [MTOK*768];  // qkv (also reused for pix output)
__device__ float g_attn[MTOK*DIM];  // attention output (pre out-proj)
__device__ float g_ff  [MTOK*1024]; // ff hidden

// ---------------- tokenize: pad + 5 shifted rolls + patchify --------------
__global__ void tokenize_kernel(const float* __restrict__ x) {
    int idx = blockIdx.x * blockDim.x + threadIdx.x;
    const int total = MTOK * 1280;
    if (idx >= total) return;
    int c = idx % 1280;
    int m = idx / 1280;
    int b = m / NTOK;
    int n = m % NTOK;
    int py = n / HP, px = n % HP;
    int s  = c / 256;
    int pr = (c % 256) / 16;
    int pc = c % 16;
    // shifts (dx,dy): (0,0),(-8,-8),(8,-8),(-8,8),(8,8); rolled[y][x]=xp[(y-dy)%H][(x-dx)%W]
    const int dxs[5] = {0, -8, 8, -8, 8};
    const int dys[5] = {0, -8, -8, 8, 8};
    int y  = py * 16 + pr - dys[s];
    int xx = px * 16 + pc - dxs[s];
    y  = (y  + HPAD) % HPAD;
    xx = (xx + HPAD) % HPAD;
    float v = 0.f;
    if (y < IMGS && xx < IMGS)
        v = x[((size_t)b * IMGS + y) * IMGS + xx];
    g_tok[idx] = v;
}

// ---------------- add positional embedding --------------------------------
__global__ void addpos_kernel(const float* __restrict__ pos) {
    int idx = blockIdx.x * blockDim.x + threadIdx.x;
    if (idx >= MTOK * DIM) return;
    int d = idx % DIM;
    int n = (idx / DIM) % NTOK;
    g_t[idx] += pos[n * DIM + d];
}

// ---------------- generic tiled SGEMM: C = act(A @ W^T + bias) [+ res] ----
// A:[M,K] row-major, W:[Nn,K] row-major. 64x64 tile, BK=16, 256 thr, 4x4/thr.
__device__ __forceinline__ float gelu_exact(float v) {
    return 0.5f * v * (1.0f + erff(v * 0.70710678118654752440f));
}

template<int ACT, bool HASBIAS, bool HASRES>
__global__ void gemm_kernel(const float* __restrict__ A, const float* __restrict__ W,
                            const float* __restrict__ bias, const float* __restrict__ res,
                            float* __restrict__ C, int M, int Nn, int K) {
    __shared__ float As[16][68];
    __shared__ float Ws[16][68];
    const int tid = threadIdx.x;
    const int tx = tid % 16, ty = tid / 16;
    const int m0 = blockIdx.y * 64, n0 = blockIdx.x * 64;
    const int lrow = tid / 4;     // 0..63
    const int lk4  = tid % 4;     // float4 index along K

    float acc[4][4] = {};

    for (int k0 = 0; k0 < K; k0 += 16) {
        float4 av = make_float4(0.f, 0.f, 0.f, 0.f);
        int am = m0 + lrow;
        if (am < M) av = *(const float4*)&A[(size_t)am * K + k0 + lk4 * 4];
        As[lk4 * 4 + 0][lrow] = av.x;
        As[lk4 * 4 + 1][lrow] = av.y;
        As[lk4 * 4 + 2][lrow] = av.z;
        As[lk4 * 4 + 3][lrow] = av.w;
        float4 wv = *(const float4*)&W[(size_t)(n0 + lrow) * K + k0 + lk4 * 4];
        Ws[lk4 * 4 + 0][lrow] = wv.x;
        Ws[lk4 * 4 + 1][lrow] = wv.y;
        Ws[lk4 * 4 + 2][lrow] = wv.z;
        Ws[lk4 * 4 + 3][lrow] = wv.w;
        __syncthreads();
        #pragma unroll
        for (int kk = 0; kk < 16; kk++) {
            float4 a  = *(const float4*)&As[kk][ty * 4];
            float4 w4 = *(const float4*)&Ws[kk][tx * 4];
            float ar[4] = {a.x, a.y, a.z, a.w};
            float wr[4] = {w4.x, w4.y, w4.z, w4.w};
            #pragma unroll
            for (int r = 0; r < 4; r++)
                #pragma unroll
                for (int c = 0; c < 4; c++)
                    acc[r][c] = fmaf(ar[r], wr[c], acc[r][c]);
        }
        __syncthreads();
    }

    #pragma unroll
    for (int r = 0; r < 4; r++) {
        int m = m0 + ty * 4 + r;
        if (m >= M) continue;
        #pragma unroll
        for (int c = 0; c < 4; c++) {
            int n = n0 + tx * 4 + c;
            float v = acc[r][c];
            if (HASBIAS) v += bias[n];
            if (ACT == 1) v = gelu_exact(v);
            if (HASRES) v += res[(size_t)m * Nn + n];
            C[(size_t)m * Nn + n] = v;
        }
    }
}

// ---------------- LayerNorm (warp per token, dim=256) ---------------------
__global__ void ln_kernel(const float* __restrict__ in, const float* __restrict__ w,
                          const float* __restrict__ b, float* __restrict__ out) {
    int warp = threadIdx.x / 32, lane = threadIdx.x % 32;
    int m = blockIdx.x * 8 + warp;
    if (m >= MTOK) return;
    const float* row = in + (size_t)m * DIM;
    float vals[8], s = 0.f, s2 = 0.f;
    #pragma unroll
    for (int k = 0; k < 8; k++) {
        float v = row[lane + 32 * k];
        vals[k] = v; s += v; s2 += v * v;
    }
    #pragma unroll
    for (int o = 16; o; o >>= 1) {
        s  += __shfl_xor_sync(0xffffffffu, s,  o);
        s2 += __shfl_xor_sync(0xffffffffu, s2, o);
    }
    float mean = s * (1.f / 256.f);
    float var  = s2 * (1.f / 256.f) - mean * mean;
    float rstd = rsqrtf(var + 1e-5f);
    float* orow = out + (size_t)m * DIM;
    #pragma unroll
    for (int k = 0; k < 8; k++) {
        int d = lane + 32 * k;
        orow[d] = (vals[k] - mean) * rstd * w[d] + b[d];
    }
}

// ---------------- masked attention (warp per query row, smem K/V tiles) ---
// attends only to j < i; row 0 -> zeros. scale per head.
#define AT_WARPS 4
#define AT_TJ    32
__global__ void attn_kernel(const float* __restrict__ scale_d) {
    int bh = blockIdx.y;
    int b = bh / NHEADS, h = bh % NHEADS;
    int warp = threadIdx.x / 32, lane = threadIdx.x % 32;
    int i = blockIdx.x * AT_WARPS + warp;

    __shared__ float kT[AT_TJ][DH];
    __shared__ float vT[AT_TJ][DH];

    const float* base = g_qkv + (size_t)b * NTOK * 768;
    const int hd = h * DH + lane;

    float q = 0.f;
    if (i < NTOK) q = base[(size_t)i * 768 + hd];
    float sc = scale_d[h];

    float mmax = -1e30f, l = 0.f, acc = 0.f;

    int imax = min(blockIdx.x * AT_WARPS + AT_WARPS - 1, NTOK - 1); // largest i in block
    for (int j0 = 0; j0 < imax; j0 += AT_TJ) {
        int nrows = min(AT_TJ, imax - j0);
        __syncthreads();
        for (int r = warp; r < nrows; r += AT_WARPS) {
            kT[r][lane] = base[(size_t)(j0 + r) * 768 + 256 + hd];
            vT[r][lane] = base[(size_t)(j0 + r) * 768 + 512 + hd];
        }
        __syncthreads();
        if (i < NTOK) {
            int jend = min(nrows, i - j0);
            for (int r = 0; r < jend; r++) {
                float s = q * kT[r][lane];
                #pragma unroll
                for (int o = 16; o; o >>= 1) s += __shfl_xor_sync(0xffffffffu, s, o);
                s *= sc;
                float mn   = fmaxf(mmax, s);
                float corr = __expf(mmax - mn);
                float p    = __expf(s - mn);
                l   = l * corr + p;
                acc = acc * corr + p * vT[r][lane];
                mmax = mn;
            }
        }
    }
    if (i < NTOK) {
        float o = (i == 0 || l == 0.f) ? 0.f : acc / l;
        g_attn[((size_t)b * NTOK + i) * DIM + hd] = o;
    }
}

// ---------------- untokenize + crop ----------------------------------------
__global__ void reshape_kernel(const float* __restrict__ pix, float* __restrict__ out) {
    int idx = blockIdx.x * blockDim.x + threadIdx.x;
    const int total = BATCH * IMGS * IMGS;
    if (idx >= total) return;
    int b   = idx / (IMGS * IMGS);
    int rem = idx % (IMGS * IMGS);
    int y = rem / IMGS, x = rem % IMGS;
    int py = y >> 4, pr = y & 15, px = x >> 4, pc = x & 15;
    int m = b * NTOK + py * HP + px;
    out[idx] = pix[(size_t)m * 256 + pr * 16 + pc];
}

// ---------------- host orchestration ---------------------------------------
static inline dim3 gemm_grid(int M, int Nn) { return dim3((Nn + 63) / 64, (M + 63) / 64); }

extern "C" void kernel_launch(void* const* d_in, const int* in_sizes, int n_in,
                              void* d_out, int out_size) {
    const float* x      = (const float*)d_in[0];
    const float* pos    = (const float*)d_in[1];
    const float* spt_w  = (const float*)d_in[2];
    const float* spt_b  = (const float*)d_in[3];
    const float* ln1_w  = (const float*)d_in[4];
    const float* ln1_b  = (const float*)d_in[5];
    const float* scale  = (const float*)d_in[6];
    const float* wqkv   = (const float*)d_in[7];
    const float* wout   = (const float*)d_in[8];
    const float* bout   = (const float*)d_in[9];
    const float* ln2_w  = (const float*)d_in[10];
    const float* ln2_b  = (const float*)d_in[11];
    const float* ff1_w  = (const float*)d_in[12];
    const float* ff1_b  = (const float*)d_in[13];
    const float* ff2_w  = (const float*)d_in[14];
    const float* ff2_b  = (const float*)d_in[15];
    const float* pix_w  = (const float*)d_in[16];
    const float* pix_b  = (const float*)d_in[17];

    float *tok, *t, *ln, *qkv, *attn, *ff;
    cudaGetSymbolAddress((void**)&tok,  g_tok);
    cudaGetSymbolAddress((void**)&t,    g_t);
    cudaGetSymbolAddress((void**)&ln,   g_ln);
    cudaGetSymbolAddress((void**)&qkv,  g_qkv);
    cudaGetSymbolAddress((void**)&attn, g_attn);
    cudaGetSymbolAddress((void**)&ff,   g_ff);

    // 1) tokenize
    {
        int total = MTOK * 1280;
        tokenize_kernel<<<(total + 255) / 256, 256>>>(x);
    }
    // 2) token projection: t = tok @ spt_w^T + spt_b
    gemm_kernel<0, true, false><<<gemm_grid(MTOK, DIM), 256>>>(
        tok, spt_w, spt_b, nullptr, t, MTOK, DIM, 1280);
    // 3) + pos_emb
    addpos_kernel<<<(MTOK * DIM + 255) / 256, 256>>>(pos);

    const int LN_BLOCKS = (MTOK + 7) / 8;
    for (int d = 0; d < 3; d++) {
        // LN1
        ln_kernel<<<LN_BLOCKS, 256>>>(t, ln1_w + d * DIM, ln1_b + d * DIM, ln);
        // QKV (no bias)
        gemm_kernel<0, false, false><<<gemm_grid(MTOK, 768), 256>>>(
            ln, wqkv + (size_t)d * 768 * DIM, nullptr, nullptr, qkv, MTOK, 768, DIM);
        // attention
        {
            dim3 grid((NTOK + AT_WARPS - 1) / AT_WARPS, BATCH * NHEADS);
            attn_kernel<<<grid, AT_WARPS * 32>>>(scale + d * NHEADS);
        }
        // out projection + residual (in-place on t)
        gemm_kernel<0, true, true><<<gemm_grid(MTOK, DIM), 256>>>(
            attn, wout + (size_t)d * DIM * DIM, bout + d * DIM, t, t, MTOK, DIM, DIM);
        // LN2
        ln_kernel<<<LN_BLOCKS, 256>>>(t, ln2_w + d * DIM, ln2_b + d * DIM, ln);
        // FF1 + exact GELU
        gemm_kernel<1, true, false><<<gemm_grid(MTOK, 1024), 256>>>(
            ln, ff1_w + (size_t)d * 1024 * DIM, ff1_b + d * 1024, nullptr, ff, MTOK, 1024, DIM);
        // FF2 + residual (in-place on t)
        gemm_kernel<0, true, true><<<gemm_grid(MTOK, DIM), 256>>>(
            ff, ff2_w + (size_t)d * DIM * 1024, ff2_b + d * DIM, t, t, MTOK, DIM, 1024);
    }

    // pix projection: reuse qkv buffer as [MTOK, 256]
    gemm_kernel<0, true, false><<<gemm_grid(MTOK, DIM), 256>>>(
        t, pix_w, pix_b, nullptr, qkv, MTOK, DIM, DIM);

    // untokenize + crop
    {
        int total = BATCH * IMGS * IMGS;
        reshape_kernel<<<(total + 255) / 256, 256>>>(qkv, (float*)d_out);
    }
}

// round 3
// speedup vs baseline: 2.0388x; 2.0388x over previous
#include <cuda_runtime.h>
#include <math.h>
#include <stdint.h>

#define IMGS   457
#define HPAD   464
#define HP     29
#define NTOK   841
#define BATCH  8
#define DIM    256
#define MTOK   (BATCH*NTOK)   // 6728
#define NHEADS 8
#define DH     32

// ---------------- scratch (device globals; no allocations) ----------------
__device__ float g_tok [MTOK*1280];
__device__ float g_t   [MTOK*DIM];
__device__ float g_ln  [MTOK*DIM];
__device__ float g_qkv [MTOK*768];
__device__ float g_attn[MTOK*DIM];
__device__ float g_ff  [MTOK*1024];

// ---------------- tokenize: pad + 5 shifted rolls + patchify --------------
__global__ void tokenize_kernel(const float* __restrict__ x) {
    int idx = blockIdx.x * blockDim.x + threadIdx.x;
    const int total = MTOK * 1280;
    if (idx >= total) return;
    int c = idx % 1280;
    int m = idx / 1280;
    int b = m / NTOK;
    int n = m % NTOK;
    int py = n / HP, px = n % HP;
    int s  = c / 256;
    int pr = (c % 256) / 16;
    int pc = c % 16;
    const int dxs[5] = {0, -8, 8, -8, 8};
    const int dys[5] = {0, -8, -8, 8, 8};
    int y  = py * 16 + pr - dys[s];
    int xx = px * 16 + pc - dxs[s];
    y  = (y  + HPAD) % HPAD;
    xx = (xx + HPAD) % HPAD;
    float v = 0.f;
    if (y < IMGS && xx < IMGS)
        v = x[((size_t)b * IMGS + y) * IMGS + xx];
    g_tok[idx] = v;
}

__global__ void addpos_kernel(const float* __restrict__ pos) {
    int idx = blockIdx.x * blockDim.x + threadIdx.x;
    if (idx >= MTOK * DIM) return;
    int d = idx % DIM;
    int n = (idx / DIM) % NTOK;
    g_t[idx] += pos[n * DIM + d];
}

// ---------------- tf32 tensor-core GEMM ------------------------------------
// C[M,Nn] = act(A[M,K] @ W[Nn,K]^T + bias) [+ res]
// BM=128 BN=64 BK=32, 256 threads (8 warps, 4x2), warp tile 32x32,
// mma.sync.m16n8k8 tf32. SMEM: As[m][k] pitch 36, Ws[n][k] pitch 36.
__device__ __forceinline__ uint32_t f2tf(float f) {
    uint32_t r;
    asm("cvt.rna.tf32.f32 %0, %1;" : "=r"(r) : "f"(f));
    return r;
}
__device__ __forceinline__ void mma_tf32(float c[4], const uint32_t a[4],
                                         uint32_t b0, uint32_t b1) {
    asm volatile(
        "mma.sync.aligned.m16n8k8.row.col.f32.tf32.tf32.f32 "
        "{%0,%1,%2,%3}, {%4,%5,%6,%7}, {%8,%9}, {%0,%1,%2,%3};"
        : "+f"(c[0]), "+f"(c[1]), "+f"(c[2]), "+f"(c[3])
        : "r"(a[0]), "r"(a[1]), "r"(a[2]), "r"(a[3]), "r"(b0), "r"(b1));
}
__device__ __forceinline__ float gelu_exact(float v) {
    return 0.5f * v * (1.0f + erff(v * 0.70710678118654752440f));
}

template<int ACT, bool HASBIAS, bool HASRES>
__global__ void __launch_bounds__(256)
gemm_tc(const float* __restrict__ A, const float* __restrict__ W,
        const float* __restrict__ bias, const float* __restrict__ res,
        float* __restrict__ C, int M, int Nn, int K) {
    __shared__ __align__(16) uint32_t As[128][36];
    __shared__ __align__(16) uint32_t Ws[64][36];
    const int tid  = threadIdx.x;
    const int wid  = tid >> 5, lane = tid & 31;
    const int wm   = wid & 3,  wn   = wid >> 2;
    const int gid  = lane >> 2, tig = lane & 3;
    const int m0   = blockIdx.y * 128, n0 = blockIdx.x * 64;

    float acc[2][4][4] = {};

    for (int k0 = 0; k0 < K; k0 += 32) {
        // A tile: 128x32 -> 1024 float4, 4 per thread
        #pragma unroll
        for (int i = 0; i < 4; i++) {
            int linear = tid + i * 256;
            int row = linear >> 3, c4 = (linear & 7) * 4;
            float4 v = make_float4(0.f, 0.f, 0.f, 0.f);
            if (m0 + row < M)
                v = *(const float4*)&A[(size_t)(m0 + row) * K + k0 + c4];
            uint4 u = make_uint4(f2tf(v.x), f2tf(v.y), f2tf(v.z), f2tf(v.w));
            *(uint4*)&As[row][c4] = u;
        }
        // W tile: 64x32 -> 512 float4, 2 per thread
        #pragma unroll
        for (int i = 0; i < 2; i++) {
            int linear = tid + i * 256;
            int row = linear >> 3, c4 = (linear & 7) * 4;
            float4 v = *(const float4*)&W[(size_t)(n0 + row) * K + k0 + c4];
            uint4 u = make_uint4(f2tf(v.x), f2tf(v.y), f2tf(v.z), f2tf(v.w));
            *(uint4*)&Ws[row][c4] = u;
        }
        __syncthreads();
        #pragma unroll
        for (int ks = 0; ks < 32; ks += 8) {
            uint32_t af[2][4];
            #pragma unroll
            for (int mt = 0; mt < 2; mt++) {
                int mb = wm * 32 + mt * 16;
                af[mt][0] = As[mb + gid    ][ks + tig];
                af[mt][1] = As[mb + gid + 8][ks + tig];
                af[mt][2] = As[mb + gid    ][ks + tig + 4];
                af[mt][3] = As[mb + gid + 8][ks + tig + 4];
            }
            #pragma unroll
            for (int nt = 0; nt < 4; nt++) {
                int nb = wn * 32 + nt * 8;
                uint32_t b0 = Ws[nb + gid][ks + tig];
                uint32_t b1 = Ws[nb + gid][ks + tig + 4];
                #pragma unroll
                for (int mt = 0; mt < 2; mt++)
                    mma_tf32(acc[mt][nt], af[mt], b0, b1);
            }
        }
        __syncthreads();
    }

    #pragma unroll
    for (int mt = 0; mt < 2; mt++) {
        #pragma unroll
        for (int half = 0; half < 2; half++) {
            int m = m0 + wm * 32 + mt * 16 + gid + half * 8;
            if (m >= M) continue;
            #pragma unroll
            for (int nt = 0; nt < 4; nt++) {
                int n = n0 + wn * 32 + nt * 8 + tig * 2;
                float v0 = acc[mt][nt][half * 2 + 0];
                float v1 = acc[mt][nt][half * 2 + 1];
                if (HASBIAS) { v0 += bias[n]; v1 += bias[n + 1]; }
                if (ACT == 1) { v0 = gelu_exact(v0); v1 = gelu_exact(v1); }
                if (HASRES) {
                    float2 r = *(const float2*)&res[(size_t)m * Nn + n];
                    v0 += r.x; v1 += r.y;
                }
                *(float2*)&C[(size_t)m * Nn + n] = make_float2(v0, v1);
            }
        }
    }
}

// ---------------- LayerNorm (warp per token, dim=256) ---------------------
__global__ void ln_kernel(const float* __restrict__ in, const float* __restrict__ w,
                          const float* __restrict__ b, float* __restrict__ out) {
    int warp = threadIdx.x / 32, lane = threadIdx.x % 32;
    int m = blockIdx.x * 8 + warp;
    if (m >= MTOK) return;
    const float* row = in + (size_t)m * DIM;
    float vals[8], s = 0.f, s2 = 0.f;
    #pragma unroll
    for (int k = 0; k < 8; k++) {
        float v = row[lane + 32 * k];
        vals[k] = v; s += v; s2 += v * v;
    }
    #pragma unroll
    for (int o = 16; o; o >>= 1) {
        s  += __shfl_xor_sync(0xffffffffu, s,  o);
        s2 += __shfl_xor_sync(0xffffffffu, s2, o);
    }
    float mean = s * (1.f / 256.f);
    float var  = s2 * (1.f / 256.f) - mean * mean;
    float rstd = rsqrtf(var + 1e-5f);
    float* orow = out + (size_t)m * DIM;
    #pragma unroll
    for (int k = 0; k < 8; k++) {
        int d = lane + 32 * k;
        orow[d] = (vals[k] - mean) * rstd * w[d] + b[d];
    }
}

// ---------------- masked attention: warp/query, lane/key tiles -------------
#define AT_WARPS 4
__global__ void attn_kernel(const float* __restrict__ scale_d) {
    __shared__ float kT[32][DH + 1];
    __shared__ float vT[32][DH + 1];
    __shared__ float qs[AT_WARPS][DH];
    __shared__ float ps[AT_WARPS][32];

    int bh = blockIdx.y;
    int b = bh / NHEADS, h = bh % NHEADS;
    int warp = threadIdx.x / 32, lane = threadIdx.x % 32;
    int i = blockIdx.x * AT_WARPS + warp;

    const float* base = g_qkv + (size_t)b * NTOK * 768;
    const int hd = h * DH + lane;
    float sc = scale_d[h];

    if (i < NTOK) qs[warp][lane] = base[(size_t)i * 768 + hd] * sc;
    __syncwarp();

    float mmax = -1e30f, l = 0.f, acc = 0.f;
    int imax = min(blockIdx.x * AT_WARPS + AT_WARPS - 1, NTOK - 1);

    for (int j0 = 0; j0 < imax; j0 += 32) {
        int nrows = min(32, imax - j0);
        __syncthreads();
        for (int r = warp; r < nrows; r += AT_WARPS) {
            kT[r][lane] = base[(size_t)(j0 + r) * 768 + 256 + hd];
            vT[r][lane] = base[(size_t)(j0 + r) * 768 + 512 + hd];
        }
        __syncthreads();
        int jcnt = min(nrows, i - j0);
        if (i < NTOK && jcnt > 0) {
            float s = -1e30f;
            if (lane < jcnt) {
                float d0 = 0.f;
                #pragma unroll
                for (int d = 0; d < DH; d++) d0 += qs[warp][d] * kT[lane][d];
                s = d0;
            }
            float tmax = s;
            #pragma unroll
            for (int o = 16; o; o >>= 1)
                tmax = fmaxf(tmax, __shfl_xor_sync(0xffffffffu, tmax, o));
            float mn = fmaxf(mmax, tmax);
            float p = (lane < jcnt) ? __expf(s - mn) : 0.f;
            float psum = p;
            #pragma unroll
            for (int o = 16; o; o >>= 1)
                psum += __shfl_xor_sync(0xffffffffu, psum, o);
            float corr = __expf(mmax - mn);
            l = l * corr + psum;
            ps[warp][lane] = p;
            __syncwarp();
            float a2 = 0.f;
            for (int j = 0; j < jcnt; j++)
                a2 += ps[warp][j] * vT[j][lane];
            acc = acc * corr + a2;
            mmax = mn;
        }
    }
    if (i < NTOK) {
        float o = (i == 0 || l == 0.f) ? 0.f : acc / l;
        g_attn[((size_t)b * NTOK + i) * DIM + hd] = o;
    }
}

// ---------------- untokenize + crop ----------------------------------------
__global__ void reshape_kernel(const float* __restrict__ pix, float* __restrict__ out) {
    int idx = blockIdx.x * blockDim.x + threadIdx.x;
    const int total = BATCH * IMGS * IMGS;
    if (idx >= total) return;
    int b   = idx / (IMGS * IMGS);
    int rem = idx % (IMGS * IMGS);
    int y = rem / IMGS, x = rem % IMGS;
    int py = y >> 4, pr = y & 15, px = x >> 4, pc = x & 15;
    int m = b * NTOK + py * HP + px;
    out[idx] = pix[(size_t)m * 256 + pr * 16 + pc];
}

// ---------------- host orchestration ---------------------------------------
static inline dim3 gemm_grid(int M, int Nn) { return dim3((Nn + 63) / 64, (M + 127) / 128); }

extern "C" void kernel_launch(void* const* d_in, const int* in_sizes, int n_in,
                              void* d_out, int out_size) {
    const float* x      = (const float*)d_in[0];
    const float* pos    = (const float*)d_in[1];
    const float* spt_w  = (const float*)d_in[2];
    const float* spt_b  = (const float*)d_in[3];
    const float* ln1_w  = (const float*)d_in[4];
    const float* ln1_b  = (const float*)d_in[5];
    const float* scale  = (const float*)d_in[6];
    const float* wqkv   = (const float*)d_in[7];
    const float* wout   = (const float*)d_in[8];
    const float* bout   = (const float*)d_in[9];
    const float* ln2_w  = (const float*)d_in[10];
    const float* ln2_b  = (const float*)d_in[11];
    const float* ff1_w  = (const float*)d_in[12];
    const float* ff1_b  = (const float*)d_in[13];
    const float* ff2_w  = (const float*)d_in[14];
    const float* ff2_b  = (const float*)d_in[15];
    const float* pix_w  = (const float*)d_in[16];
    const float* pix_b  = (const float*)d_in[17];

    float *tok, *t, *ln, *qkv, *attn, *ff;
    cudaGetSymbolAddress((void**)&tok,  g_tok);
    cudaGetSymbolAddress((void**)&t,    g_t);
    cudaGetSymbolAddress((void**)&ln,   g_ln);
    cudaGetSymbolAddress((void**)&qkv,  g_qkv);
    cudaGetSymbolAddress((void**)&attn, g_attn);
    cudaGetSymbolAddress((void**)&ff,   g_ff);

    {
        int total = MTOK * 1280;
        tokenize_kernel<<<(total + 255) / 256, 256>>>(x);
    }
    gemm_tc<0, true, false><<<gemm_grid(MTOK, DIM), 256>>>(
        tok, spt_w, spt_b, nullptr, t, MTOK, DIM, 1280);
    addpos_kernel<<<(MTOK * DIM + 255) / 256, 256>>>(pos);

    const int LN_BLOCKS = (MTOK + 7) / 8;
    for (int d = 0; d < 3; d++) {
        ln_kernel<<<LN_BLOCKS, 256>>>(t, ln1_w + d * DIM, ln1_b + d * DIM, ln);
        gemm_tc<0, false, false><<<gemm_grid(MTOK, 768), 256>>>(
            ln, wqkv + (size_t)d * 768 * DIM, nullptr, nullptr, qkv, MTOK, 768, DIM);
        {
            dim3 grid((NTOK + AT_WARPS - 1) / AT_WARPS, BATCH * NHEADS);
            attn_kernel<<<grid, AT_WARPS * 32>>>(scale + d * NHEADS);
        }
        gemm_tc<0, true, true><<<gemm_grid(MTOK, DIM), 256>>>(
            attn, wout + (size_t)d * DIM * DIM, bout + d * DIM, t, t, MTOK, DIM, DIM);
        ln_kernel<<<LN_BLOCKS, 256>>>(t, ln2_w + d * DIM, ln2_b + d * DIM, ln);
        gemm_tc<1, true, false><<<gemm_grid(MTOK, 1024), 256>>>(
            ln, ff1_w + (size_t)d * 1024 * DIM, ff1_b + d * 1024, nullptr, ff, MTOK, 1024, DIM);
        gemm_tc<0, true, true><<<gemm_grid(MTOK, DIM), 256>>>(
            ff, ff2_w + (size_t)d * DIM * 1024, ff2_b + d * DIM, t, t, MTOK, DIM, 1024);
    }

    gemm_tc<0, true, false><<<gemm_grid(MTOK, DIM), 256>>>(
        t, pix_w, pix_b, nullptr, qkv, MTOK, DIM, DIM);

    {
        int total = BATCH * IMGS * IMGS;
        reshape_kernel<<<(total + 255) / 256, 256>>>(qkv, (float*)d_out);
    }
}

// round 4
// speedup vs baseline: 2.1202x; 1.0399x over previous
#include <cuda_runtime.h>
#include <math.h>
#include <stdint.h>

#define IMGS   457
#define HPAD   464
#define HP     29
#define NTOK   841
#define BATCH  8
#define DIM    256
#define MTOK   (BATCH*NTOK)   // 6728
#define NHEADS 8
#define DH     32

// ---------------- scratch (device globals; no allocations) ----------------
__device__ float g_tok [MTOK*1280];
__device__ float g_t   [MTOK*DIM];
__device__ float g_ln  [MTOK*DIM];
__device__ float g_qkv [MTOK*768];
__device__ float g_attn[MTOK*DIM];
__device__ float g_ff  [MTOK*1024];

// ---------------- tokenize: pad + 5 shifted rolls + patchify --------------
__global__ void tokenize_kernel(const float* __restrict__ x) {
    int idx = blockIdx.x * blockDim.x + threadIdx.x;
    const int total = MTOK * 1280;
    if (idx >= total) return;
    int c = idx % 1280;
    int m = idx / 1280;
    int b = m / NTOK;
    int n = m % NTOK;
    int py = n / HP, px = n % HP;
    int s  = c / 256;
    int pr = (c % 256) / 16;
    int pc = c % 16;
    const int dxs[5] = {0, -8, 8, -8, 8};
    const int dys[5] = {0, -8, -8, 8, 8};
    int y  = py * 16 + pr - dys[s];
    int xx = px * 16 + pc - dxs[s];
    y  = (y  + HPAD) % HPAD;
    xx = (xx + HPAD) % HPAD;
    float v = 0.f;
    if (y < IMGS && xx < IMGS)
        v = x[((size_t)b * IMGS + y) * IMGS + xx];
    g_tok[idx] = v;
}

// ---------------- tf32 tensor-core GEMM, cp.async double-buffered ---------
// C[M,Nn] = act(A[M,K] @ W[Nn,K]^T + bias) [+ res]
// BM=128 BN=64 BK=32, 256 threads (8 warps: 4 m-tiles x 2 n-tiles of 32x32).
// SMEM: XOR-swizzled (col ^ 4*(row&7)), 2 stages, exactly 48 KB.
__device__ __forceinline__ uint32_t f2tf(float f) {
    uint32_t r;
    asm("cvt.rna.tf32.f32 %0, %1;" : "=r"(r) : "f"(f));
    return r;
}
__device__ __forceinline__ void mma_tf32(float c[4], const uint32_t a[4],
                                         uint32_t b0, uint32_t b1) {
    asm volatile(
        "mma.sync.aligned.m16n8k8.row.col.f32.tf32.tf32.f32 "
        "{%0,%1,%2,%3}, {%4,%5,%6,%7}, {%8,%9}, {%0,%1,%2,%3};"
        : "+f"(c[0]), "+f"(c[1]), "+f"(c[2]), "+f"(c[3])
        : "r"(a[0]), "r"(a[1]), "r"(a[2]), "r"(a[3]), "r"(b0), "r"(b1));
}
__device__ __forceinline__ float gelu_exact(float v) {
    return 0.5f * v * (1.0f + erff(v * 0.70710678118654752440f));
}
__device__ __forceinline__ void cp16(uint32_t saddr, const float* g, bool pred) {
    asm volatile("cp.async.cg.shared.global [%0], [%1], 16, %2;"
                 :: "r"(saddr), "l"(g), "r"(pred ? 16 : 0));
}
__device__ __forceinline__ void cp_commit() {
    asm volatile("cp.async.commit_group;");
}
template<int N>
__device__ __forceinline__ void cp_wait() {
    asm volatile("cp.async.wait_group %0;" :: "n"(N));
}
__device__ __forceinline__ int swz(int row, int col) {
    return row * 32 + (col ^ ((row & 7) * 4));
}

template<int ACT, bool HASBIAS, bool HASRES, bool POSMOD>
__global__ void __launch_bounds__(256)
gemm_tc(const float* __restrict__ A, const float* __restrict__ W,
        const float* __restrict__ bias, const float* __restrict__ res,
        float* __restrict__ C, int M, int Nn, int K) {
    __shared__ float As[2][128 * 32];
    __shared__ float Ws[2][64 * 32];
    const int tid  = threadIdx.x;
    const int wid  = tid >> 5, lane = tid & 31;
    const int wm   = wid & 3,  wn   = wid >> 2;
    const int gid  = lane >> 2, tig = lane & 3;
    const int m0   = blockIdx.y * 128, n0 = blockIdx.x * 64;

    const int arow = tid >> 3;            // 0..31 per 256-chunk step
    const int ac4  = (tid & 7) * 4;       // float4 column

    uint32_t As_base = (uint32_t)__cvta_generic_to_shared(&As[0][0]);
    uint32_t Ws_base = (uint32_t)__cvta_generic_to_shared(&Ws[0][0]);

    float acc[2][4][4] = {};
    const int ktiles = K >> 5;

    // --- tile loader ---
    auto load_tile = [&](int kt, int buf) {
        const float* Ag = A + (size_t)(m0) * K + kt * 32;
        #pragma unroll
        for (int i = 0; i < 4; i++) {
            int row = arow + i * 32;
            uint32_t s = As_base + (buf * 128 * 32 + swz(row, ac4)) * 4;
            cp16(s, Ag + (size_t)row * K + ac4, (m0 + row) < M);
        }
        const float* Wg = W + (size_t)(n0) * K + kt * 32;
        #pragma unroll
        for (int i = 0; i < 2; i++) {
            int row = arow + i * 32;
            uint32_t s = Ws_base + (buf * 64 * 32 + swz(row, ac4)) * 4;
            cp16(s, Wg + (size_t)row * K + ac4, true);
        }
    };

    load_tile(0, 0);
    cp_commit();

    for (int kt = 0; kt < ktiles; kt++) {
        int cur = kt & 1;
        if (kt + 1 < ktiles) { load_tile(kt + 1, cur ^ 1); cp_commit(); cp_wait<1>(); }
        else                 { cp_wait<0>(); }
        __syncthreads();

        const float* as = &As[cur][0];
        const float* ws = &Ws[cur][0];
        #pragma unroll
        for (int ks = 0; ks < 32; ks += 8) {
            uint32_t af[2][4];
            #pragma unroll
            for (int mt = 0; mt < 2; mt++) {
                int r0 = wm * 32 + mt * 16 + gid;
                af[mt][0] = f2tf(as[swz(r0,     ks + tig)]);
                af[mt][1] = f2tf(as[swz(r0 + 8, ks + tig)]);
                af[mt][2] = f2tf(as[swz(r0,     ks + tig + 4)]);
                af[mt][3] = f2tf(as[swz(r0 + 8, ks + tig + 4)]);
            }
            #pragma unroll
            for (int nt = 0; nt < 4; nt++) {
                int nr = wn * 32 + nt * 8 + gid;
                uint32_t b0 = f2tf(ws[swz(nr, ks + tig)]);
                uint32_t b1 = f2tf(ws[swz(nr, ks + tig + 4)]);
                #pragma unroll
                for (int mt = 0; mt < 2; mt++)
                    mma_tf32(acc[mt][nt], af[mt], b0, b1);
            }
        }
        __syncthreads();
    }

    #pragma unroll
    for (int mt = 0; mt < 2; mt++) {
        #pragma unroll
        for (int half = 0; half < 2; half++) {
            int m = m0 + wm * 32 + mt * 16 + gid + half * 8;
            if (m >= M) continue;
            int mres = POSMOD ? (m % NTOK) : m;
            #pragma unroll
            for (int nt = 0; nt < 4; nt++) {
                int n = n0 + wn * 32 + nt * 8 + tig * 2;
                float v0 = acc[mt][nt][half * 2 + 0];
                float v1 = acc[mt][nt][half * 2 + 1];
                if (HASBIAS) { v0 += bias[n]; v1 += bias[n + 1]; }
                if (ACT == 1) { v0 = gelu_exact(v0); v1 = gelu_exact(v1); }
                if (HASRES) {
                    float2 r = *(const float2*)&res[(size_t)mres * Nn + n];
                    v0 += r.x; v1 += r.y;
                }
                *(float2*)&C[(size_t)m * Nn + n] = make_float2(v0, v1);
            }
        }
    }
}

// ---------------- LayerNorm (warp per token, dim=256) ---------------------
__global__ void ln_kernel(const float* __restrict__ in, const float* __restrict__ w,
                          const float* __restrict__ b, float* __restrict__ out) {
    int warp = threadIdx.x / 32, lane = threadIdx.x % 32;
    int m = blockIdx.x * 8 + warp;
    if (m >= MTOK) return;
    const float* row = in + (size_t)m * DIM;
    float vals[8], s = 0.f, s2 = 0.f;
    #pragma unroll
    for (int k = 0; k < 8; k++) {
        float v = row[lane + 32 * k];
        vals[k] = v; s += v; s2 += v * v;
    }
    #pragma unroll
    for (int o = 16; o; o >>= 1) {
        s  += __shfl_xor_sync(0xffffffffu, s,  o);
        s2 += __shfl_xor_sync(0xffffffffu, s2, o);
    }
    float mean = s * (1.f / 256.f);
    float var  = s2 * (1.f / 256.f) - mean * mean;
    float rstd = rsqrtf(var + 1e-5f);
    float* orow = out + (size_t)m * DIM;
    #pragma unroll
    for (int k = 0; k < 8; k++) {
        int d = lane + 32 * k;
        orow[d] = (vals[k] - mean) * rstd * w[d] + b[d];
    }
}

// ---------------- masked attention: warp/query, lane/key tiles -------------
#define AT_WARPS 4
__global__ void attn_kernel(const float* __restrict__ scale_d) {
    __shared__ float kT[32][DH + 1];
    __shared__ float vT[32][DH + 1];
    __shared__ float qs[AT_WARPS][DH];
    __shared__ float ps[AT_WARPS][32];

    int bh = blockIdx.y;
    int b = bh / NHEADS, h = bh % NHEADS;
    int warp = threadIdx.x / 32, lane = threadIdx.x % 32;
    int i = blockIdx.x * AT_WARPS + warp;

    const float* base = g_qkv + (size_t)b * NTOK * 768;
    const int hd = h * DH + lane;
    float sc = scale_d[h];

    if (i < NTOK) qs[warp][lane] = base[(size_t)i * 768 + hd] * sc;
    __syncwarp();

    float mmax = -1e30f, l = 0.f, acc = 0.f;
    int imax = min(blockIdx.x * AT_WARPS + AT_WARPS - 1, NTOK - 1);

    for (int j0 = 0; j0 < imax; j0 += 32) {
        int nrows = min(32, imax - j0);
        __syncthreads();
        for (int r = warp; r < nrows; r += AT_WARPS) {
            kT[r][lane] = base[(size_t)(j0 + r) * 768 + 256 + hd];
            vT[r][lane] = base[(size_t)(j0 + r) * 768 + 512 + hd];
        }
        __syncthreads();
        int jcnt = min(nrows, i - j0);
        if (i < NTOK && jcnt > 0) {
            float s = -1e30f;
            if (lane < jcnt) {
                float d0 = 0.f;
                #pragma unroll
                for (int d = 0; d < DH; d++) d0 += qs[warp][d] * kT[lane][d];
                s = d0;
            }
            float tmax = s;
            #pragma unroll
            for (int o = 16; o; o >>= 1)
                tmax = fmaxf(tmax, __shfl_xor_sync(0xffffffffu, tmax, o));
            float mn = fmaxf(mmax, tmax);
            float p = (lane < jcnt) ? __expf(s - mn) : 0.f;
            float psum = p;
            #pragma unroll
            for (int o = 16; o; o >>= 1)
                psum += __shfl_xor_sync(0xffffffffu, psum, o);
            float corr = __expf(mmax - mn);
            l = l * corr + psum;
            ps[warp][lane] = p;
            __syncwarp();
            float a2 = 0.f;
            for (int j = 0; j < jcnt; j++)
                a2 += ps[warp][j] * vT[j][lane];
            acc = acc * corr + a2;
            mmax = mn;
        }
    }
    if (i < NTOK) {
        float o = (i == 0 || l == 0.f) ? 0.f : acc / l;
        g_attn[((size_t)b * NTOK + i) * DIM + hd] = o;
    }
}

// ---------------- untokenize + crop ----------------------------------------
__global__ void reshape_kernel(const float* __restrict__ pix, float* __restrict__ out) {
    int idx = blockIdx.x * blockDim.x + threadIdx.x;
    const int total = BATCH * IMGS * IMGS;
    if (idx >= total) return;
    int b   = idx / (IMGS * IMGS);
    int rem = idx % (IMGS * IMGS);
    int y = rem / IMGS, x = rem % IMGS;
    int py = y >> 4, pr = y & 15, px = x >> 4, pc = x & 15;
    int m = b * NTOK + py * HP + px;
    out[idx] = pix[(size_t)m * 256 + pr * 16 + pc];
}

// ---------------- host orchestration ---------------------------------------
static inline dim3 gemm_grid(int M, int Nn) { return dim3((Nn + 63) / 64, (M + 127) / 128); }

extern "C" void kernel_launch(void* const* d_in, const int* in_sizes, int n_in,
                              void* d_out, int out_size) {
    const float* x      = (const float*)d_in[0];
    const float* pos    = (const float*)d_in[1];
    const float* spt_w  = (const float*)d_in[2];
    const float* spt_b  = (const float*)d_in[3];
    const float* ln1_w  = (const float*)d_in[4];
    const float* ln1_b  = (const float*)d_in[5];
    const float* scale  = (const float*)d_in[6];
    const float* wqkv   = (const float*)d_in[7];
    const float* wout   = (const float*)d_in[8];
    const float* bout   = (const float*)d_in[9];
    const float* ln2_w  = (const float*)d_in[10];
    const float* ln2_b  = (const float*)d_in[11];
    const float* ff1_w  = (const float*)d_in[12];
    const float* ff1_b  = (const float*)d_in[13];
    const float* ff2_w  = (const float*)d_in[14];
    const float* ff2_b  = (const float*)d_in[15];
    const float* pix_w  = (const float*)d_in[16];
    const float* pix_b  = (const float*)d_in[17];

    float *tok, *t, *ln, *qkv, *attn, *ff;
    cudaGetSymbolAddress((void**)&tok,  g_tok);
    cudaGetSymbolAddress((void**)&t,    g_t);
    cudaGetSymbolAddress((void**)&ln,   g_ln);
    cudaGetSymbolAddress((void**)&qkv,  g_qkv);
    cudaGetSymbolAddress((void**)&attn, g_attn);
    cudaGetSymbolAddress((void**)&ff,   g_ff);

    {
        int total = MTOK * 1280;
        tokenize_kernel<<<(total + 255) / 256, 256>>>(x);
    }
    // spt projection with fused pos_emb residual (row index m % NTOK)
    gemm_tc<0, true, true, true><<<gemm_grid(MTOK, DIM), 256>>>(
        tok, spt_w, spt_b, pos, t, MTOK, DIM, 1280);

    const int LN_BLOCKS = (MTOK + 7) / 8;
    for (int d = 0; d < 3; d++) {
        ln_kernel<<<LN_BLOCKS, 256>>>(t, ln1_w + d * DIM, ln1_b + d * DIM, ln);
        gemm_tc<0, false, false, false><<<gemm_grid(MTOK, 768), 256>>>(
            ln, wqkv + (size_t)d * 768 * DIM, nullptr, nullptr, qkv, MTOK, 768, DIM);
        {
            dim3 grid((NTOK + AT_WARPS - 1) / AT_WARPS, BATCH * NHEADS);
            attn_kernel<<<grid, AT_WARPS * 32>>>(scale + d * NHEADS);
        }
        gemm_tc<0, true, true, false><<<gemm_grid(MTOK, DIM), 256>>>(
            attn, wout + (size_t)d * DIM * DIM, bout + d * DIM, t, t, MTOK, DIM, DIM);
        ln_kernel<<<LN_BLOCKS, 256>>>(t, ln2_w + d * DIM, ln2_b + d * DIM, ln);
        gemm_tc<1, true, false, false><<<gemm_grid(MTOK, 1024), 256>>>(
            ln, ff1_w + (size_t)d * 1024 * DIM, ff1_b + d * 1024, nullptr, ff, MTOK, 1024, DIM);
        gemm_tc<0, true, true, false><<<gemm_grid(MTOK, DIM), 256>>>(
            ff, ff2_w + (size_t)d * DIM * 1024, ff2_b + d * DIM, t, t, MTOK, DIM, 1024);
    }

    gemm_tc<0, true, false, false><<<gemm_grid(MTOK, DIM), 256>>>(
        t, pix_w, pix_b, nullptr, qkv, MTOK, DIM, DIM);

    {
        int total = BATCH * IMGS * IMGS;
        reshape_kernel<<<(total + 255) / 256, 256>>>(qkv, (float*)d_out);
    }
}

// round 5
// speedup vs baseline: 5.5535x; 2.6193x over previous
#include <cuda_runtime.h>
#include <math.h>
#include <stdint.h>

#define IMGS   457
#define HPAD   464
#define HP     29
#define NTOK   841
#define BATCH  8
#define DIM    256
#define MTOK   (BATCH*NTOK)   // 6728
#define NHEADS 8
#define DH     32

// ---------------- scratch (device globals; no allocations) ----------------
__device__ float g_tok [MTOK*1280];
__device__ float g_t   [MTOK*DIM];
__device__ float g_ln  [MTOK*DIM];
__device__ float g_qkv [MTOK*768];
__device__ float g_attn[MTOK*DIM];
__device__ float g_ff  [MTOK*1024];

// pre-truncated (tf32) weights
#define W_SPT_OFF  0
#define W_SPT_SZ   (256*1280)
#define W_QKV_OFF  (W_SPT_OFF+W_SPT_SZ)
#define W_QKV_SZ   (3*768*256)
#define W_WOUT_OFF (W_QKV_OFF+W_QKV_SZ)
#define W_WOUT_SZ  (3*256*256)
#define W_FF1_OFF  (W_WOUT_OFF+W_WOUT_SZ)
#define W_FF1_SZ   (3*1024*256)
#define W_FF2_OFF  (W_FF1_OFF+W_FF1_SZ)
#define W_FF2_SZ   (3*256*1024)
#define W_PIX_OFF  (W_FF2_OFF+W_FF2_SZ)
#define W_PIX_SZ   (256*256)
#define W_TOTAL    (W_PIX_OFF+W_PIX_SZ)
__device__ float g_wtf[W_TOTAL];

__device__ __forceinline__ uint32_t f2tf(float f) {
    uint32_t r;
    asm("cvt.rna.tf32.f32 %0, %1;" : "=r"(r) : "f"(f));
    return r;
}
__device__ __forceinline__ float ftrunc_tf(float f) { return __uint_as_float(f2tf(f)); }

__global__ void convert_w(const float* __restrict__ spt, const float* __restrict__ qkv,
                          const float* __restrict__ wo, const float* __restrict__ f1,
                          const float* __restrict__ f2w, const float* __restrict__ px) {
    int i4 = blockIdx.x * 256 + threadIdx.x;
    if (i4 >= W_TOTAL / 4) return;
    int i = i4 * 4;
    const float* src; int off;
    if      (i < W_QKV_OFF)  { src = spt; off = 0; }
    else if (i < W_WOUT_OFF) { src = qkv; off = W_QKV_OFF; }
    else if (i < W_FF1_OFF)  { src = wo;  off = W_WOUT_OFF; }
    else if (i < W_FF2_OFF)  { src = f1;  off = W_FF1_OFF; }
    else if (i < W_PIX_OFF)  { src = f2w; off = W_FF2_OFF; }
    else                     { src = px;  off = W_PIX_OFF; }
    float4 v = *(const float4*)(src + (i - off));
    v.x = ftrunc_tf(v.x); v.y = ftrunc_tf(v.y);
    v.z = ftrunc_tf(v.z); v.w = ftrunc_tf(v.w);
    *(float4*)&g_wtf[i] = v;
}

// ---------------- tokenize: pad + 5 shifted rolls + patchify --------------
__global__ void tokenize_kernel(const float* __restrict__ x) {
    int idx = blockIdx.x * blockDim.x + threadIdx.x;
    const int total = MTOK * 1280;
    if (idx >= total) return;
    int c = idx % 1280;
    int m = idx / 1280;
    int b = m / NTOK;
    int n = m % NTOK;
    int py = n / HP, px = n % HP;
    int s  = c / 256;
    int pr = (c % 256) / 16;
    int pc = c % 16;
    const int dxs[5] = {0, -8, 8, -8, 8};
    const int dys[5] = {0, -8, -8, 8, 8};
    int y  = py * 16 + pr - dys[s];
    int xx = px * 16 + pc - dxs[s];
    y  = (y  + HPAD) % HPAD;
    xx = (xx + HPAD) % HPAD;
    float v = 0.f;
    if (y < IMGS && xx < IMGS)
        v = x[((size_t)b * IMGS + y) * IMGS + xx];
    g_tok[idx] = ftrunc_tf(v);
}

// ---------------- tf32 tensor-core GEMM, cp.async double-buffered ---------
__device__ __forceinline__ void mma_tf32(float c[4], const uint32_t a[4],
                                         uint32_t b0, uint32_t b1) {
    asm volatile(
        "mma.sync.aligned.m16n8k8.row.col.f32.tf32.tf32.f32 "
        "{%0,%1,%2,%3}, {%4,%5,%6,%7}, {%8,%9}, {%0,%1,%2,%3};"
        : "+f"(c[0]), "+f"(c[1]), "+f"(c[2]), "+f"(c[3])
        : "r"(a[0]), "r"(a[1]), "r"(a[2]), "r"(a[3]), "r"(b0), "r"(b1));
}
__device__ __forceinline__ float gelu_exact(float v) {
    return 0.5f * v * (1.0f + erff(v * 0.70710678118654752440f));
}
__device__ __forceinline__ void cp16(uint32_t saddr, const float* g, bool pred) {
    asm volatile("cp.async.cg.shared.global [%0], [%1], 16, %2;"
                 :: "r"(saddr), "l"(g), "r"(pred ? 16 : 0));
}
__device__ __forceinline__ void cp_commit() { asm volatile("cp.async.commit_group;"); }
template<int N>
__device__ __forceinline__ void cp_wait() {
    asm volatile("cp.async.wait_group %0;" :: "n"(N));
}
__device__ __forceinline__ int swz(int row, int col) {
    return row * 32 + (col ^ ((row & 7) * 4));
}

template<int ACT, bool HASBIAS, bool HASRES, bool POSMOD, bool CVTA, bool TRUNC>
__global__ void __launch_bounds__(256)
gemm_tc(const float* __restrict__ A, const float* __restrict__ W,
        const float* __restrict__ bias, const float* __restrict__ res,
        float* __restrict__ C, int M, int Nn, int K) {
    __shared__ float As[2][128 * 32];
    __shared__ float Ws[2][64 * 32];
    const int tid  = threadIdx.x;
    const int wid  = tid >> 5, lane = tid & 31;
    const int wm   = wid & 3,  wn   = wid >> 2;
    const int gid  = lane >> 2, tig = lane & 3;
    const int m0   = blockIdx.y * 128, n0 = blockIdx.x * 64;

    const int arow = tid >> 3;
    const int ac4  = (tid & 7) * 4;

    uint32_t As_base = (uint32_t)__cvta_generic_to_shared(&As[0][0]);
    uint32_t Ws_base = (uint32_t)__cvta_generic_to_shared(&Ws[0][0]);

    float acc[2][4][4] = {};
    const int ktiles = K >> 5;

    auto load_tile = [&](int kt, int buf) {
        const float* Ag = A + (size_t)m0 * K + kt * 32;
        #pragma unroll
        for (int i = 0; i < 4; i++) {
            int row = arow + i * 32;
            uint32_t s = As_base + (buf * 128 * 32 + swz(row, ac4)) * 4;
            cp16(s, Ag + (size_t)row * K + ac4, (m0 + row) < M);
        }
        const float* Wg = W + (size_t)n0 * K + kt * 32;
        #pragma unroll
        for (int i = 0; i < 2; i++) {
            int row = arow + i * 32;
            uint32_t s = Ws_base + (buf * 64 * 32 + swz(row, ac4)) * 4;
            cp16(s, Wg + (size_t)row * K + ac4, true);
        }
    };

    load_tile(0, 0);
    cp_commit();

    for (int kt = 0; kt < ktiles; kt++) {
        int cur = kt & 1;
        if (kt + 1 < ktiles) { load_tile(kt + 1, cur ^ 1); cp_commit(); cp_wait<1>(); }
        else                 { cp_wait<0>(); }
        __syncthreads();

        const float* as = &As[cur][0];
        const float* ws = &Ws[cur][0];
        #pragma unroll
        for (int ks = 0; ks < 32; ks += 8) {
            uint32_t af[2][4];
            #pragma unroll
            for (int mt = 0; mt < 2; mt++) {
                int r0 = wm * 32 + mt * 16 + gid;
                if (CVTA) {
                    af[mt][0] = f2tf(as[swz(r0,     ks + tig)]);
                    af[mt][1] = f2tf(as[swz(r0 + 8, ks + tig)]);
                    af[mt][2] = f2tf(as[swz(r0,     ks + tig + 4)]);
                    af[mt][3] = f2tf(as[swz(r0 + 8, ks + tig + 4)]);
                } else {
                    af[mt][0] = __float_as_uint(as[swz(r0,     ks + tig)]);
                    af[mt][1] = __float_as_uint(as[swz(r0 + 8, ks + tig)]);
                    af[mt][2] = __float_as_uint(as[swz(r0,     ks + tig + 4)]);
                    af[mt][3] = __float_as_uint(as[swz(r0 + 8, ks + tig + 4)]);
                }
            }
            #pragma unroll
            for (int nt = 0; nt < 4; nt++) {
                int nr = wn * 32 + nt * 8 + gid;
                uint32_t b0 = __float_as_uint(ws[swz(nr, ks + tig)]);
                uint32_t b1 = __float_as_uint(ws[swz(nr, ks + tig + 4)]);
                #pragma unroll
                for (int mt = 0; mt < 2; mt++)
                    mma_tf32(acc[mt][nt], af[mt], b0, b1);
            }
        }
        __syncthreads();
    }

    #pragma unroll
    for (int mt = 0; mt < 2; mt++) {
        #pragma unroll
        for (int half = 0; half < 2; half++) {
            int m = m0 + wm * 32 + mt * 16 + gid + half * 8;
            if (m >= M) continue;
            int mres = POSMOD ? (m % NTOK) : m;
            #pragma unroll
            for (int nt = 0; nt < 4; nt++) {
                int n = n0 + wn * 32 + nt * 8 + tig * 2;
                float v0 = acc[mt][nt][half * 2 + 0];
                float v1 = acc[mt][nt][half * 2 + 1];
                if (HASBIAS) { v0 += bias[n]; v1 += bias[n + 1]; }
                if (ACT == 1) { v0 = gelu_exact(v0); v1 = gelu_exact(v1); }
                if (HASRES) {
                    float2 r = *(const float2*)&res[(size_t)mres * Nn + n];
                    v0 += r.x; v1 += r.y;
                }
                if (TRUNC) { v0 = ftrunc_tf(v0); v1 = ftrunc_tf(v1); }
                *(float2*)&C[(size_t)m * Nn + n] = make_float2(v0, v1);
            }
        }
    }
}

// ---------------- LayerNorm (warp per token, dim=256, tf32-truncated out) --
__global__ void ln_kernel(const float* __restrict__ in, const float* __restrict__ w,
                          const float* __restrict__ b, float* __restrict__ out) {
    int warp = threadIdx.x / 32, lane = threadIdx.x % 32;
    int m = blockIdx.x * 8 + warp;
    if (m >= MTOK) return;
    const float* row = in + (size_t)m * DIM;
    float vals[8], s = 0.f, s2 = 0.f;
    #pragma unroll
    for (int k = 0; k < 8; k++) {
        float v = row[lane + 32 * k];
        vals[k] = v; s += v; s2 += v * v;
    }
    #pragma unroll
    for (int o = 16; o; o >>= 1) {
        s  += __shfl_xor_sync(0xffffffffu, s,  o);
        s2 += __shfl_xor_sync(0xffffffffu, s2, o);
    }
    float mean = s * (1.f / 256.f);
    float var  = s2 * (1.f / 256.f) - mean * mean;
    float rstd = rsqrtf(var + 1e-5f);
    float* orow = out + (size_t)m * DIM;
    #pragma unroll
    for (int k = 0; k < 8; k++) {
        int d = lane + 32 * k;
        orow[d] = ftrunc_tf((vals[k] - mean) * rstd * w[d] + b[d]);
    }
}

// ---------------- MMA flash attention --------------------------------------
// block: 64 queries x one (b,h); 4 warps, 16 rows each. tf32 mma for QK^T & PV.
__global__ void __launch_bounds__(128)
attn_mma(const float* __restrict__ scale_d) {
    __shared__ uint32_t Ks[32 * 36];
    __shared__ uint32_t Vs[32 * 40];
    __shared__ uint32_t Ps[4][16 * 36];

    const int bh = blockIdx.y;
    const int b = bh >> 3, h = bh & 7;
    const int warp = threadIdx.x >> 5, lane = threadIdx.x & 31;
    const int gid = lane >> 2, tig = lane & 3;
    const int q0 = blockIdx.x * 64;
    const float* base = g_qkv + (size_t)b * NTOK * 768;
    const float sc = scale_d[h];

    const int i0 = q0 + warp * 16 + gid;
    const int i1 = i0 + 8;

    uint32_t qf[4][4];
    #pragma unroll
    for (int ks = 0; ks < 4; ks++) {
        int c = h * 32 + ks * 8 + tig;
        float v00 = 0.f, v10 = 0.f, v01 = 0.f, v11 = 0.f;
        if (i0 < NTOK) { v00 = base[(size_t)i0 * 768 + c] * sc;
                         v01 = base[(size_t)i0 * 768 + c + 4] * sc; }
        if (i1 < NTOK) { v10 = base[(size_t)i1 * 768 + c] * sc;
                         v11 = base[(size_t)i1 * 768 + c + 4] * sc; }
        qf[ks][0] = f2tf(v00); qf[ks][1] = f2tf(v10);
        qf[ks][2] = f2tf(v01); qf[ks][3] = f2tf(v11);
    }

    float m0 = -1e30f, m1 = -1e30f, l0 = 0.f, l1 = 0.f;
    float oacc[4][4] = {};

    const int jmax = min(q0 + 63, NTOK - 1);
    for (int j0 = 0; j0 < jmax; j0 += 32) {
        __syncthreads();
        {
            int r  = threadIdx.x >> 2;
            int c8 = (threadIdx.x & 3) * 8;
            int j  = j0 + r;
            if (j < NTOK) {
                const float* kp = base + (size_t)j * 768 + 256 + h * 32 + c8;
                const float* vp = base + (size_t)j * 768 + 512 + h * 32 + c8;
                float4 ka = *(const float4*)kp, kb = *(const float4*)(kp + 4);
                Ks[r * 36 + c8 + 0] = f2tf(ka.x); Ks[r * 36 + c8 + 1] = f2tf(ka.y);
                Ks[r * 36 + c8 + 2] = f2tf(ka.z); Ks[r * 36 + c8 + 3] = f2tf(ka.w);
                Ks[r * 36 + c8 + 4] = f2tf(kb.x); Ks[r * 36 + c8 + 5] = f2tf(kb.y);
                Ks[r * 36 + c8 + 6] = f2tf(kb.z); Ks[r * 36 + c8 + 7] = f2tf(kb.w);
                float4 va = *(const float4*)vp, vb = *(const float4*)(vp + 4);
                Vs[r * 40 + c8 + 0] = f2tf(va.x); Vs[r * 40 + c8 + 1] = f2tf(va.y);
                Vs[r * 40 + c8 + 2] = f2tf(va.z); Vs[r * 40 + c8 + 3] = f2tf(va.w);
                Vs[r * 40 + c8 + 4] = f2tf(vb.x); Vs[r * 40 + c8 + 5] = f2tf(vb.y);
                Vs[r * 40 + c8 + 6] = f2tf(vb.z); Vs[r * 40 + c8 + 7] = f2tf(vb.w);
            } else {
                #pragma unroll
                for (int q = 0; q < 8; q++) {
                    Ks[r * 36 + c8 + q] = 0;
                    Vs[r * 40 + c8 + q] = 0;
                }
            }
        }
        __syncthreads();

        float s[4][4] = {};
        #pragma unroll
        for (int ks = 0; ks < 4; ks++) {
            #pragma unroll
            for (int nt = 0; nt < 4; nt++) {
                uint32_t b0 = Ks[(nt * 8 + gid) * 36 + ks * 8 + tig];
                uint32_t b1 = Ks[(nt * 8 + gid) * 36 + ks * 8 + tig + 4];
                mma_tf32(s[nt], qf[ks], b0, b1);
            }
        }

        float rm0 = -1e30f, rm1 = -1e30f;
        #pragma unroll
        for (int nt = 0; nt < 4; nt++) {
            int jc = j0 + nt * 8 + tig * 2;
            if (jc     >= i0) s[nt][0] = -1e30f;
            if (jc + 1 >= i0) s[nt][1] = -1e30f;
            if (jc     >= i1) s[nt][2] = -1e30f;
            if (jc + 1 >= i1) s[nt][3] = -1e30f;
            rm0 = fmaxf(rm0, fmaxf(s[nt][0], s[nt][1]));
            rm1 = fmaxf(rm1, fmaxf(s[nt][2], s[nt][3]));
        }
        rm0 = fmaxf(rm0, __shfl_xor_sync(0xffffffffu, rm0, 1));
        rm0 = fmaxf(rm0, __shfl_xor_sync(0xffffffffu, rm0, 2));
        rm1 = fmaxf(rm1, __shfl_xor_sync(0xffffffffu, rm1, 1));
        rm1 = fmaxf(rm1, __shfl_xor_sync(0xffffffffu, rm1, 2));
        float mn0 = fmaxf(m0, rm0), mn1 = fmaxf(m1, rm1);
        float corr0 = __expf(m0 - mn0), corr1 = __expf(m1 - mn1);

        float p[4][4];
        float ps0 = 0.f, ps1 = 0.f;
        #pragma unroll
        for (int nt = 0; nt < 4; nt++) {
            p[nt][0] = (s[nt][0] < -1e29f) ? 0.f : __expf(s[nt][0] - mn0);
            p[nt][1] = (s[nt][1] < -1e29f) ? 0.f : __expf(s[nt][1] - mn0);
            p[nt][2] = (s[nt][2] < -1e29f) ? 0.f : __expf(s[nt][2] - mn1);
            p[nt][3] = (s[nt][3] < -1e29f) ? 0.f : __expf(s[nt][3] - mn1);
            ps0 += p[nt][0] + p[nt][1];
            ps1 += p[nt][2] + p[nt][3];
        }
        ps0 += __shfl_xor_sync(0xffffffffu, ps0, 1);
        ps0 += __shfl_xor_sync(0xffffffffu, ps0, 2);
        ps1 += __shfl_xor_sync(0xffffffffu, ps1, 1);
        ps1 += __shfl_xor_sync(0xffffffffu, ps1, 2);
        l0 = l0 * corr0 + ps0;
        l1 = l1 * corr1 + ps1;
        #pragma unroll
        for (int nt = 0; nt < 4; nt++) {
            oacc[nt][0] *= corr0; oacc[nt][1] *= corr0;
            oacc[nt][2] *= corr1; oacc[nt][3] *= corr1;
        }

        uint32_t* pw = Ps[warp];
        __syncwarp();
        #pragma unroll
        for (int nt = 0; nt < 4; nt++) {
            pw[gid * 36 + nt * 8 + tig * 2    ]  = f2tf(p[nt][0]);
            pw[gid * 36 + nt * 8 + tig * 2 + 1]  = f2tf(p[nt][1]);
            pw[(gid + 8) * 36 + nt * 8 + tig * 2    ] = f2tf(p[nt][2]);
            pw[(gid + 8) * 36 + nt * 8 + tig * 2 + 1] = f2tf(p[nt][3]);
        }
        __syncwarp();

        #pragma unroll
        for (int ks = 0; ks < 4; ks++) {
            uint32_t af[4];
            af[0] = pw[gid * 36 + ks * 8 + tig];
            af[1] = pw[(gid + 8) * 36 + ks * 8 + tig];
            af[2] = pw[gid * 36 + ks * 8 + tig + 4];
            af[3] = pw[(gid + 8) * 36 + ks * 8 + tig + 4];
            #pragma unroll
            for (int nt = 0; nt < 4; nt++) {
                uint32_t b0 = Vs[(ks * 8 + tig) * 40 + nt * 8 + gid];
                uint32_t b1 = Vs[(ks * 8 + tig + 4) * 40 + nt * 8 + gid];
                mma_tf32(oacc[nt], af, b0, b1);
            }
        }
        m0 = mn0; m1 = mn1;
    }

    float inv0 = (l0 > 0.f) ? 1.f / l0 : 0.f;
    float inv1 = (l1 > 0.f) ? 1.f / l1 : 0.f;
    #pragma unroll
    for (int nt = 0; nt < 4; nt++) {
        int col = h * 32 + nt * 8 + tig * 2;
        if (i0 < NTOK) {
            float2 o = make_float2(ftrunc_tf(oacc[nt][0] * inv0),
                                   ftrunc_tf(oacc[nt][1] * inv0));
            *(float2*)&g_attn[((size_t)b * NTOK + i0) * DIM + col] = o;
        }
        if (i1 < NTOK) {
            float2 o = make_float2(ftrunc_tf(oacc[nt][2] * inv1),
                                   ftrunc_tf(oacc[nt][3] * inv1));
            *(float2*)&g_attn[((size_t)b * NTOK + i1) * DIM + col] = o;
        }
    }
}

// ---------------- untokenize + crop ----------------------------------------
__global__ void reshape_kernel(const float* __restrict__ pix, float* __restrict__ out) {
    int idx = blockIdx.x * blockDim.x + threadIdx.x;
    const int total = BATCH * IMGS * IMGS;
    if (idx >= total) return;
    int b   = idx / (IMGS * IMGS);
    int rem = idx % (IMGS * IMGS);
    int y = rem / IMGS, x = rem % IMGS;
    int py = y >> 4, pr = y & 15, px = x >> 4, pc = x & 15;
    int m = b * NTOK + py * HP + px;
    out[idx] = pix[(size_t)m * 256 + pr * 16 + pc];
}

// ---------------- host orchestration ---------------------------------------
static inline dim3 gemm_grid(int M, int Nn) { return dim3((Nn + 63) / 64, (M + 127) / 128); }

extern "C" void kernel_launch(void* const* d_in, const int* in_sizes, int n_in,
                              void* d_out, int out_size) {
    const float* x      = (const float*)d_in[0];
    const float* pos    = (const float*)d_in[1];
    const float* spt_w  = (const float*)d_in[2];
    const float* spt_b  = (const float*)d_in[3];
    const float* ln1_w  = (const float*)d_in[4];
    const float* ln1_b  = (const float*)d_in[5];
    const float* scale  = (const float*)d_in[6];
    const float* wqkv   = (const float*)d_in[7];
    const float* wout   = (const float*)d_in[8];
    const float* bout   = (const float*)d_in[9];
    const float* ln2_w  = (const float*)d_in[10];
    const float* ln2_b  = (const float*)d_in[11];
    const float* ff1_w  = (const float*)d_in[12];
    const float* ff1_b  = (const float*)d_in[13];
    const float* ff2_w  = (const float*)d_in[14];
    const float* ff2_b  = (const float*)d_in[15];
    const float* pix_w  = (const float*)d_in[16];
    const float* pix_b  = (const float*)d_in[17];

    float *tok, *t, *ln, *qkv, *attn, *ff, *wtf;
    cudaGetSymbolAddress((void**)&tok,  g_tok);
    cudaGetSymbolAddress((void**)&t,    g_t);
    cudaGetSymbolAddress((void**)&ln,   g_ln);
    cudaGetSymbolAddress((void**)&qkv,  g_qkv);
    cudaGetSymbolAddress((void**)&attn, g_attn);
    cudaGetSymbolAddress((void**)&ff,   g_ff);
    cudaGetSymbolAddress((void**)&wtf,  g_wtf);

    convert_w<<<(W_TOTAL / 4 + 255) / 256, 256>>>(spt_w, wqkv, wout, ff1_w, ff2_w, pix_w);
    {
        int total = MTOK * 1280;
        tokenize_kernel<<<(total + 255) / 256, 256>>>(x);
    }
    gemm_tc<0, true, true, true, false, false><<<gemm_grid(MTOK, DIM), 256>>>(
        tok, wtf + W_SPT_OFF, spt_b, pos, t, MTOK, DIM, 1280);

    const int LN_BLOCKS = (MTOK + 7) / 8;
    for (int d = 0; d < 3; d++) {
        ln_kernel<<<LN_BLOCKS, 256>>>(t, ln1_w + d * DIM, ln1_b + d * DIM, ln);
        gemm_tc<0, false, false, false, false, false><<<gemm_grid(MTOK, 768), 256>>>(
            ln, wtf + W_QKV_OFF + (size_t)d * 768 * DIM, nullptr, nullptr, qkv, MTOK, 768, DIM);
        {
            dim3 grid((NTOK + 63) / 64, BATCH * NHEADS);
            attn_mma<<<grid, 128>>>(scale + d * NHEADS);
        }
        gemm_tc<0, true, true, false, false, false><<<gemm_grid(MTOK, DIM), 256>>>(
            attn, wtf + W_WOUT_OFF + (size_t)d * DIM * DIM, bout + d * DIM, t, t, MTOK, DIM, DIM);
        ln_kernel<<<LN_BLOCKS, 256>>>(t, ln2_w + d * DIM, ln2_b + d * DIM, ln);
        gemm_tc<1, true, false, false, false, true><<<gemm_grid(MTOK, 1024), 256>>>(
            ln, wtf + W_FF1_OFF + (size_t)d * 1024 * DIM, ff1_b + d * 1024, nullptr, ff, MTOK, 1024, DIM);
        gemm_tc<0, true, true, false, false, false><<<gemm_grid(MTOK, DIM), 256>>>(
            ff, wtf + W_FF2_OFF + (size_t)d * DIM * 1024, ff2_b + d * DIM, t, t, MTOK, DIM, 1024);
    }

    gemm_tc<0, true, false, false, true, false><<<gemm_grid(MTOK, DIM), 256>>>(
        t, wtf + W_PIX_OFF, pix_b, nullptr, qkv, MTOK, DIM, DIM);

    {
        int total = BATCH * IMGS * IMGS;
        reshape_kernel<<<(total + 255) / 256, 256>>>(qkv, (float*)d_out);
    }
}

// round 6
// speedup vs baseline: 5.5697x; 1.0029x over previous
#include <cuda_runtime.h>
#include <math.h>
#include <stdint.h>

#define IMGS   457
#define HPAD   464
#define HP     29
#define NTOK   841
#define BATCH  8
#define DIM    256
#define MTOK   (BATCH*NTOK)   // 6728
#define NHEADS 8
#define DH     32

// ---------------- scratch (device globals; no allocations) ----------------
__device__ float g_tok [MTOK*1280];
__device__ float g_t   [MTOK*DIM];
__device__ float g_ln  [MTOK*DIM];
__device__ float g_qkv [MTOK*768];
__device__ float g_attn[MTOK*DIM];
__device__ float g_ff  [MTOK*1024];

// pre-truncated (tf32) weights
#define W_SPT_OFF  0
#define W_SPT_SZ   (256*1280)
#define W_QKV_OFF  (W_SPT_OFF+W_SPT_SZ)
#define W_QKV_SZ   (3*768*256)
#define W_WOUT_OFF (W_QKV_OFF+W_QKV_SZ)
#define W_WOUT_SZ  (3*256*256)
#define W_FF1_OFF  (W_WOUT_OFF+W_WOUT_SZ)
#define W_FF1_SZ   (3*1024*256)
#define W_FF2_OFF  (W_FF1_OFF+W_FF1_SZ)
#define W_FF2_SZ   (3*256*1024)
#define W_PIX_OFF  (W_FF2_OFF+W_FF2_SZ)
#define W_PIX_SZ   (256*256)
#define W_TOTAL    (W_PIX_OFF+W_PIX_SZ)
__device__ float g_wtf[W_TOTAL];

__device__ __forceinline__ uint32_t f2tf(float f) {
    uint32_t r;
    asm("cvt.rna.tf32.f32 %0, %1;" : "=r"(r) : "f"(f));
    return r;
}
__device__ __forceinline__ float ftrunc_tf(float f) { return __uint_as_float(f2tf(f)); }

__global__ void convert_w(const float* __restrict__ spt, const float* __restrict__ qkv,
                          const float* __restrict__ wo, const float* __restrict__ f1,
                          const float* __restrict__ f2w, const float* __restrict__ px) {
    int i4 = blockIdx.x * 256 + threadIdx.x;
    if (i4 >= W_TOTAL / 4) return;
    int i = i4 * 4;
    const float* src; int off;
    if      (i < W_QKV_OFF)  { src = spt; off = 0; }
    else if (i < W_WOUT_OFF) { src = qkv; off = W_QKV_OFF; }
    else if (i < W_FF1_OFF)  { src = wo;  off = W_WOUT_OFF; }
    else if (i < W_FF2_OFF)  { src = f1;  off = W_FF1_OFF; }
    else if (i < W_PIX_OFF)  { src = f2w; off = W_FF2_OFF; }
    else                     { src = px;  off = W_PIX_OFF; }
    float4 v = *(const float4*)(src + (i - off));
    v.x = ftrunc_tf(v.x); v.y = ftrunc_tf(v.y);
    v.z = ftrunc_tf(v.z); v.w = ftrunc_tf(v.w);
    *(float4*)&g_wtf[i] = v;
}

// ---------------- tokenize: pad + 5 shifted rolls + patchify --------------
__global__ void tokenize_kernel(const float* __restrict__ x) {
    int idx = blockIdx.x * blockDim.x + threadIdx.x;
    const int total = MTOK * 1280;
    if (idx >= total) return;
    int c = idx % 1280;
    int m = idx / 1280;
    int b = m / NTOK;
    int n = m % NTOK;
    int py = n / HP, px = n % HP;
    int s  = c / 256;
    int pr = (c % 256) / 16;
    int pc = c % 16;
    const int dxs[5] = {0, -8, 8, -8, 8};
    const int dys[5] = {0, -8, -8, 8, 8};
    int y  = py * 16 + pr - dys[s];
    int xx = px * 16 + pc - dxs[s];
    y  = (y  + HPAD) % HPAD;
    xx = (xx + HPAD) % HPAD;
    float v = 0.f;
    if (y < IMGS && xx < IMGS)
        v = x[((size_t)b * IMGS + y) * IMGS + xx];
    g_tok[idx] = ftrunc_tf(v);
}

// ---------------- tf32 tensor-core GEMM, 3-stage cp.async, 128x128 tiles ---
__device__ __forceinline__ void mma_tf32(float c[4], const uint32_t a[4],
                                         uint32_t b0, uint32_t b1) {
    asm volatile(
        "mma.sync.aligned.m16n8k8.row.col.f32.tf32.tf32.f32 "
        "{%0,%1,%2,%3}, {%4,%5,%6,%7}, {%8,%9}, {%0,%1,%2,%3};"
        : "+f"(c[0]), "+f"(c[1]), "+f"(c[2]), "+f"(c[3])
        : "r"(a[0]), "r"(a[1]), "r"(a[2]), "r"(a[3]), "r"(b0), "r"(b1));
}
__device__ __forceinline__ float gelu_exact(float v) {
    return 0.5f * v * (1.0f + erff(v * 0.70710678118654752440f));
}
__device__ __forceinline__ void cp16(uint32_t saddr, const float* g, bool pred) {
    asm volatile("cp.async.cg.shared.global [%0], [%1], 16, %2;"
                 :: "r"(saddr), "l"(g), "r"(pred ? 16 : 0));
}
__device__ __forceinline__ void cp_commit() { asm volatile("cp.async.commit_group;"); }
template<int N>
__device__ __forceinline__ void cp_wait() {
    asm volatile("cp.async.wait_group %0;" :: "n"(N));
}
__device__ __forceinline__ int swz(int row, int col) {
    return row * 32 + (col ^ ((row & 7) * 4));
}

#define GEMM_SMEM (6 * 4096 * 4)   // 3 stages x (A 128x32 + W 128x32) floats

template<int ACT, bool HASBIAS, bool HASRES, bool POSMOD, bool TRUNC>
__global__ void __launch_bounds__(256)
gemm_tc(const float* __restrict__ A, const float* __restrict__ W,
        const float* __restrict__ bias, const float* __restrict__ res,
        float* __restrict__ C, int M, int Nn, int K) {
    extern __shared__ float smem[];
    float* As = smem;               // [3][128*32]
    float* Ws = smem + 3 * 4096;    // [3][128*32]
    const int tid  = threadIdx.x;
    const int wid  = tid >> 5, lane = tid & 31;
    const int wm   = wid & 3,  wn   = wid >> 2;
    const int gid  = lane >> 2, tig = lane & 3;
    const int m0   = blockIdx.y * 128, n0 = blockIdx.x * 128;

    const int lrow = tid >> 3;
    const int lc4  = (tid & 7) * 4;

    uint32_t As_base = (uint32_t)__cvta_generic_to_shared(As);
    uint32_t Ws_base = (uint32_t)__cvta_generic_to_shared(Ws);

    float acc[2][8][4] = {};
    const int ktiles = K >> 5;

    auto load_tile = [&](int kt, int buf) {
        const float* Ag = A + (size_t)m0 * K + kt * 32;
        #pragma unroll
        for (int i = 0; i < 4; i++) {
            int row = lrow + i * 32;
            uint32_t s = As_base + (buf * 4096 + swz(row, lc4)) * 4;
            cp16(s, Ag + (size_t)row * K + lc4, (m0 + row) < M);
        }
        const float* Wg = W + (size_t)n0 * K + kt * 32;
        #pragma unroll
        for (int i = 0; i < 4; i++) {
            int row = lrow + i * 32;
            uint32_t s = Ws_base + (buf * 4096 + swz(row, lc4)) * 4;
            cp16(s, Wg + (size_t)row * K + lc4, true);
        }
    };

    load_tile(0, 0);
    cp_commit();
    if (ktiles > 1) { load_tile(1, 1); cp_commit(); }

    for (int kt = 0; kt < ktiles; kt++) {
        if (kt + 2 < ktiles) {
            load_tile(kt + 2, (kt + 2) % 3);
            cp_commit();
            cp_wait<2>();
        } else if (kt + 1 < ktiles) {
            cp_wait<1>();
        } else {
            cp_wait<0>();
        }
        __syncthreads();

        const float* as = As + (kt % 3) * 4096;
        const float* ws = Ws + (kt % 3) * 4096;
        #pragma unroll
        for (int ks = 0; ks < 32; ks += 8) {
            uint32_t af[2][4];
            #pragma unroll
            for (int mt = 0; mt < 2; mt++) {
                int r0 = wm * 32 + mt * 16 + gid;
                af[mt][0] = __float_as_uint(as[swz(r0,     ks + tig)]);
                af[mt][1] = __float_as_uint(as[swz(r0 + 8, ks + tig)]);
                af[mt][2] = __float_as_uint(as[swz(r0,     ks + tig + 4)]);
                af[mt][3] = __float_as_uint(as[swz(r0 + 8, ks + tig + 4)]);
            }
            #pragma unroll
            for (int nt = 0; nt < 8; nt++) {
                int nr = wn * 64 + nt * 8 + gid;
                uint32_t b0 = __float_as_uint(ws[swz(nr, ks + tig)]);
                uint32_t b1 = __float_as_uint(ws[swz(nr, ks + tig + 4)]);
                #pragma unroll
                for (int mt = 0; mt < 2; mt++)
                    mma_tf32(acc[mt][nt], af[mt], b0, b1);
            }
        }
        __syncthreads();
    }

    #pragma unroll
    for (int mt = 0; mt < 2; mt++) {
        #pragma unroll
        for (int half = 0; half < 2; half++) {
            int m = m0 + wm * 32 + mt * 16 + gid + half * 8;
            if (m >= M) continue;
            int mres = POSMOD ? (m % NTOK) : m;
            #pragma unroll
            for (int nt = 0; nt < 8; nt++) {
                int n = n0 + wn * 64 + nt * 8 + tig * 2;
                float v0 = acc[mt][nt][half * 2 + 0];
                float v1 = acc[mt][nt][half * 2 + 1];
                if (HASBIAS) { v0 += bias[n]; v1 += bias[n + 1]; }
                if (ACT == 1) { v0 = gelu_exact(v0); v1 = gelu_exact(v1); }
                if (HASRES) {
                    float2 r = *(const float2*)&res[(size_t)mres * Nn + n];
                    v0 += r.x; v1 += r.y;
                }
                if (TRUNC) { v0 = ftrunc_tf(v0); v1 = ftrunc_tf(v1); }
                *(float2*)&C[(size_t)m * Nn + n] = make_float2(v0, v1);
            }
        }
    }
}

// ---------------- LayerNorm (warp per token, dim=256, tf32-truncated out) --
__global__ void ln_kernel(const float* __restrict__ in, const float* __restrict__ w,
                          const float* __restrict__ b, float* __restrict__ out) {
    int warp = threadIdx.x / 32, lane = threadIdx.x % 32;
    int m = blockIdx.x * 8 + warp;
    if (m >= MTOK) return;
    const float* row = in + (size_t)m * DIM;
    float vals[8], s = 0.f, s2 = 0.f;
    #pragma unroll
    for (int k = 0; k < 8; k++) {
        float v = row[lane + 32 * k];
        vals[k] = v; s += v; s2 += v * v;
    }
    #pragma unroll
    for (int o = 16; o; o >>= 1) {
        s  += __shfl_xor_sync(0xffffffffu, s,  o);
        s2 += __shfl_xor_sync(0xffffffffu, s2, o);
    }
    float mean = s * (1.f / 256.f);
    float var  = s2 * (1.f / 256.f) - mean * mean;
    float rstd = rsqrtf(var + 1e-5f);
    float* orow = out + (size_t)m * DIM;
    #pragma unroll
    for (int k = 0; k < 8; k++) {
        int d = lane + 32 * k;
        orow[d] = ftrunc_tf((vals[k] - mean) * rstd * w[d] + b[d]);
    }
}

// ---------------- MMA flash attention, q-tile 128, 8 warps ----------------
__global__ void __launch_bounds__(256)
attn_mma(const float* __restrict__ scale_d) {
    __shared__ uint32_t Ks[32 * 36];
    __shared__ uint32_t Vs[32 * 40];
    __shared__ uint32_t Ps[8][16 * 36];

    const int bh = blockIdx.y;
    const int b = bh >> 3, h = bh & 7;
    const int tid = threadIdx.x;
    const int warp = tid >> 5, lane = tid & 31;
    const int gid = lane >> 2, tig = lane & 3;
    const int q0 = blockIdx.x * 128;
    const float* base = g_qkv + (size_t)b * NTOK * 768;
    const float sc = scale_d[h];

    const int i0 = q0 + warp * 16 + gid;
    const int i1 = i0 + 8;

    uint32_t qf[4][4];
    #pragma unroll
    for (int ks = 0; ks < 4; ks++) {
        int c = h * 32 + ks * 8 + tig;
        float v00 = 0.f, v10 = 0.f, v01 = 0.f, v11 = 0.f;
        if (i0 < NTOK) { v00 = base[(size_t)i0 * 768 + c] * sc;
                         v01 = base[(size_t)i0 * 768 + c + 4] * sc; }
        if (i1 < NTOK) { v10 = base[(size_t)i1 * 768 + c] * sc;
                         v11 = base[(size_t)i1 * 768 + c + 4] * sc; }
        qf[ks][0] = f2tf(v00); qf[ks][1] = f2tf(v10);
        qf[ks][2] = f2tf(v01); qf[ks][3] = f2tf(v11);
    }

    float m0 = -1e30f, m1 = -1e30f, l0 = 0.f, l1 = 0.f;
    float oacc[4][4] = {};

    const int jmax = min(q0 + 127, NTOK - 1);
    for (int j0 = 0; j0 < jmax; j0 += 32) {
        __syncthreads();
        {
            int r  = tid >> 3;           // 0..31
            int c4 = (tid & 7) * 4;      // 0..28 step 4
            int j  = j0 + r;
            if (j < NTOK) {
                const float* kp = base + (size_t)j * 768 + 256 + h * 32 + c4;
                const float* vp = base + (size_t)j * 768 + 512 + h * 32 + c4;
                float4 ka = *(const float4*)kp;
                Ks[r * 36 + c4 + 0] = f2tf(ka.x); Ks[r * 36 + c4 + 1] = f2tf(ka.y);
                Ks[r * 36 + c4 + 2] = f2tf(ka.z); Ks[r * 36 + c4 + 3] = f2tf(ka.w);
                float4 va = *(const float4*)vp;
                Vs[r * 40 + c4 + 0] = f2tf(va.x); Vs[r * 40 + c4 + 1] = f2tf(va.y);
                Vs[r * 40 + c4 + 2] = f2tf(va.z); Vs[r * 40 + c4 + 3] = f2tf(va.w);
            } else {
                #pragma unroll
                for (int q = 0; q < 4; q++) {
                    Ks[r * 36 + c4 + q] = 0;
                    Vs[r * 40 + c4 + q] = 0;
                }
            }
        }
        __syncthreads();

        float s[4][4] = {};
        #pragma unroll
        for (int ks = 0; ks < 4; ks++) {
            #pragma unroll
            for (int nt = 0; nt < 4; nt++) {
                uint32_t b0 = Ks[(nt * 8 + gid) * 36 + ks * 8 + tig];
                uint32_t b1 = Ks[(nt * 8 + gid) * 36 + ks * 8 + tig + 4];
                mma_tf32(s[nt], qf[ks], b0, b1);
            }
        }

        float rm0 = -1e30f, rm1 = -1e30f;
        #pragma unroll
        for (int nt = 0; nt < 4; nt++) {
            int jc = j0 + nt * 8 + tig * 2;
            if (jc     >= i0) s[nt][0] = -1e30f;
            if (jc + 1 >= i0) s[nt][1] = -1e30f;
            if (jc     >= i1) s[nt][2] = -1e30f;
            if (jc + 1 >= i1) s[nt][3] = -1e30f;
            rm0 = fmaxf(rm0, fmaxf(s[nt][0], s[nt][1]));
            rm1 = fmaxf(rm1, fmaxf(s[nt][2], s[nt][3]));
        }
        rm0 = fmaxf(rm0, __shfl_xor_sync(0xffffffffu, rm0, 1));
        rm0 = fmaxf(rm0, __shfl_xor_sync(0xffffffffu, rm0, 2));
        rm1 = fmaxf(rm1, __shfl_xor_sync(0xffffffffu, rm1, 1));
        rm1 = fmaxf(rm1, __shfl_xor_sync(0xffffffffu, rm1, 2));
        float mn0 = fmaxf(m0, rm0), mn1 = fmaxf(m1, rm1);
        float corr0 = __expf(m0 - mn0), corr1 = __expf(m1 - mn1);

        float p[4][4];
        float ps0 = 0.f, ps1 = 0.f;
        #pragma unroll
        for (int nt = 0; nt < 4; nt++) {
            p[nt][0] = (s[nt][0] < -1e29f) ? 0.f : __expf(s[nt][0] - mn0);
            p[nt][1] = (s[nt][1] < -1e29f) ? 0.f : __expf(s[nt][1] - mn0);
            p[nt][2] = (s[nt][2] < -1e29f) ? 0.f : __expf(s[nt][2] - mn1);
            p[nt][3] = (s[nt][3] < -1e29f) ? 0.f : __expf(s[nt][3] - mn1);
            ps0 += p[nt][0] + p[nt][1];
            ps1 += p[nt][2] + p[nt][3];
        }
        ps0 += __shfl_xor_sync(0xffffffffu, ps0, 1);
        ps0 += __shfl_xor_sync(0xffffffffu, ps0, 2);
        ps1 += __shfl_xor_sync(0xffffffffu, ps1, 1);
        ps1 += __shfl_xor_sync(0xffffffffu, ps1, 2);
        l0 = l0 * corr0 + ps0;
        l1 = l1 * corr1 + ps1;
        #pragma unroll
        for (int nt = 0; nt < 4; nt++) {
            oacc[nt][0] *= corr0; oacc[nt][1] *= corr0;
            oacc[nt][2] *= corr1; oacc[nt][3] *= corr1;
        }

        uint32_t* pw = Ps[warp];
        __syncwarp();
        #pragma unroll
        for (int nt = 0; nt < 4; nt++) {
            pw[gid * 36 + nt * 8 + tig * 2    ]  = f2tf(p[nt][0]);
            pw[gid * 36 + nt * 8 + tig * 2 + 1]  = f2tf(p[nt][1]);
            pw[(gid + 8) * 36 + nt * 8 + tig * 2    ] = f2tf(p[nt][2]);
            pw[(gid + 8) * 36 + nt * 8 + tig * 2 + 1] = f2tf(p[nt][3]);
        }
        __syncwarp();

        #pragma unroll
        for (int ks = 0; ks < 4; ks++) {
            uint32_t af[4];
            af[0] = pw[gid * 36 + ks * 8 + tig];
            af[1] = pw[(gid + 8) * 36 + ks * 8 + tig];
            af[2] = pw[gid * 36 + ks * 8 + tig + 4];
            af[3] = pw[(gid + 8) * 36 + ks * 8 + tig + 4];
            #pragma unroll
            for (int nt = 0; nt < 4; nt++) {
                uint32_t b0 = Vs[(ks * 8 + tig) * 40 + nt * 8 + gid];
                uint32_t b1 = Vs[(ks * 8 + tig + 4) * 40 + nt * 8 + gid];
                mma_tf32(oacc[nt], af, b0, b1);
            }
        }
        m0 = mn0; m1 = mn1;
    }

    float inv0 = (l0 > 0.f) ? 1.f / l0 : 0.f;
    float inv1 = (l1 > 0.f) ? 1.f / l1 : 0.f;
    #pragma unroll
    for (int nt = 0; nt < 4; nt++) {
        int col = h * 32 + nt * 8 + tig * 2;
        if (i0 < NTOK) {
            float2 o = make_float2(ftrunc_tf(oacc[nt][0] * inv0),
                                   ftrunc_tf(oacc[nt][1] * inv0));
            *(float2*)&g_attn[((size_t)b * NTOK + i0) * DIM + col] = o;
        }
        if (i1 < NTOK) {
            float2 o = make_float2(ftrunc_tf(oacc[nt][2] * inv1),
                                   ftrunc_tf(oacc[nt][3] * inv1));
            *(float2*)&g_attn[((size_t)b * NTOK + i1) * DIM + col] = o;
        }
    }
}

// ---------------- untokenize + crop ----------------------------------------
__global__ void reshape_kernel(const float* __restrict__ pix, float* __restrict__ out) {
    int idx = blockIdx.x * blockDim.x + threadIdx.x;
    const int total = BATCH * IMGS * IMGS;
    if (idx >= total) return;
    int b   = idx / (IMGS * IMGS);
    int rem = idx % (IMGS * IMGS);
    int y = rem / IMGS, x = rem % IMGS;
    int py = y >> 4, pr = y & 15, px = x >> 4, pc = x & 15;
    int m = b * NTOK + py * HP + px;
    out[idx] = pix[(size_t)m * 256 + pr * 16 + pc];
}

// ---------------- host orchestration ---------------------------------------
static inline dim3 gemm_grid(int M, int Nn) { return dim3((Nn + 127) / 128, (M + 127) / 128); }

extern "C" void kernel_launch(void* const* d_in, const int* in_sizes, int n_in,
                              void* d_out, int out_size) {
    const float* x      = (const float*)d_in[0];
    const float* pos    = (const float*)d_in[1];
    const float* spt_w  = (const float*)d_in[2];
    const float* spt_b  = (const float*)d_in[3];
    const float* ln1_w  = (const float*)d_in[4];
    const float* ln1_b  = (const float*)d_in[5];
    const float* scale  = (const float*)d_in[6];
    const float* wqkv   = (const float*)d_in[7];
    const float* wout   = (const float*)d_in[8];
    const float* bout   = (const float*)d_in[9];
    const float* ln2_w  = (const float*)d_in[10];
    const float* ln2_b  = (const float*)d_in[11];
    const float* ff1_w  = (const float*)d_in[12];
    const float* ff1_b  = (const float*)d_in[13];
    const float* ff2_w  = (const float*)d_in[14];
    const float* ff2_b  = (const float*)d_in[15];
    const float* pix_w  = (const float*)d_in[16];
    const float* pix_b  = (const float*)d_in[17];

    float *tok, *t, *ln, *qkv, *attn, *ff, *wtf;
    cudaGetSymbolAddress((void**)&tok,  g_tok);
    cudaGetSymbolAddress((void**)&t,    g_t);
    cudaGetSymbolAddress((void**)&ln,   g_ln);
    cudaGetSymbolAddress((void**)&qkv,  g_qkv);
    cudaGetSymbolAddress((void**)&attn, g_attn);
    cudaGetSymbolAddress((void**)&ff,   g_ff);
    cudaGetSymbolAddress((void**)&wtf,  g_wtf);

    // raise dynamic smem limits (idempotent)
    cudaFuncSetAttribute(gemm_tc<0, true,  true,  true,  false>, cudaFuncAttributeMaxDynamicSharedMemorySize, GEMM_SMEM);
    cudaFuncSetAttribute(gemm_tc<0, false, false, false, false>, cudaFuncAttributeMaxDynamicSharedMemorySize, GEMM_SMEM);
    cudaFuncSetAttribute(gemm_tc<0, true,  true,  false, false>, cudaFuncAttributeMaxDynamicSharedMemorySize, GEMM_SMEM);
    cudaFuncSetAttribute(gemm_tc<1, true,  false, false, true >, cudaFuncAttributeMaxDynamicSharedMemorySize, GEMM_SMEM);
    cudaFuncSetAttribute(gemm_tc<0, true,  false, false, false>, cudaFuncAttributeMaxDynamicSharedMemorySize, GEMM_SMEM);

    convert_w<<<(W_TOTAL / 4 + 255) / 256, 256>>>(spt_w, wqkv, wout, ff1_w, ff2_w, pix_w);
    {
        int total = MTOK * 1280;
        tokenize_kernel<<<(total + 255) / 256, 256>>>(x);
    }
    gemm_tc<0, true, true, true, false><<<gemm_grid(MTOK, DIM), 256, GEMM_SMEM>>>(
        tok, wtf + W_SPT_OFF, spt_b, pos, t, MTOK, DIM, 1280);

    const int LN_BLOCKS = (MTOK + 7) / 8;
    for (int d = 0; d < 3; d++) {
        ln_kernel<<<LN_BLOCKS, 256>>>(t, ln1_w + d * DIM, ln1_b + d * DIM, ln);
        gemm_tc<0, false, false, false, false><<<gemm_grid(MTOK, 768), 256, GEMM_SMEM>>>(
            ln, wtf + W_QKV_OFF + (size_t)d * 768 * DIM, nullptr, nullptr, qkv, MTOK, 768, DIM);
        {
            dim3 grid((NTOK + 127) / 128, BATCH * NHEADS);
            attn_mma<<<grid, 256>>>(scale + d * NHEADS);
        }
        gemm_tc<0, true, true, false, false><<<gemm_grid(MTOK, DIM), 256, GEMM_SMEM>>>(
            attn, wtf + W_WOUT_OFF + (size_t)d * DIM * DIM, bout + d * DIM, t, t, MTOK, DIM, DIM);
        ln_kernel<<<LN_BLOCKS, 256>>>(t, ln2_w + d * DIM, ln2_b + d * DIM, ln);
        gemm_tc<1, true, false, false, true><<<gemm_grid(MTOK, 1024), 256, GEMM_SMEM>>>(
            ln, wtf + W_FF1_OFF + (size_t)d * 1024 * DIM, ff1_b + d * 1024, nullptr, ff, MTOK, 1024, DIM);
        gemm_tc<0, true, true, false, false><<<gemm_grid(MTOK, DIM), 256, GEMM_SMEM>>>(
            ff, wtf + W_FF2_OFF + (size_t)d * DIM * 1024, ff2_b + d * DIM, t, t, MTOK, DIM, 1024);
    }

    gemm_tc<0, true, false, false, false><<<gemm_grid(MTOK, DIM), 256, GEMM_SMEM>>>(
        t, wtf + W_PIX_OFF, pix_b, nullptr, qkv, MTOK, DIM, DIM);

    {
        int total = BATCH * IMGS * IMGS;
        reshape_kernel<<<(total + 255) / 256, 256>>>(qkv, (float*)d_out);
    }
}